// round 4
// baseline (speedup 1.0000x reference)
#include <cuda_runtime.h>
#include <cuda_bf16.h>
#include <cstdint>

// ---------------- problem dims ----------------
#define B_DIM 512
#define NIN   64
#define DIN   128
#define NOUT  64
#define DOUT  128
#define KSEL  4
#define YCOLS (NOUT * DOUT)        // 8192
#define YELEMS (B_DIM * YCOLS)     // 4194304
#define BN_EPS 1e-5f

#define KD      (KSEL * DIN)       // 512 (logical K per head)
#define NCHUNK  24                 // 3 splits x 4 k-sel x 2 half-DIN; 64 bf16 per chunk
#define NMT     4                  // M-tiles per head (partial-stats slots)

// ---------------- scratch (device globals; no allocation allowed) ----------------
__device__ __align__(16) float          g_y[YELEMS];                 // 16.8 MB
__device__ __align__(16) __nv_bfloat16  g_xhi[B_DIM * NIN * DIN];    // 8.4 MB
__device__ __align__(16) __nv_bfloat16  g_xlo[B_DIM * NIN * DIN];
__device__ __align__(16) __nv_bfloat16  g_wthi[NOUT * DOUT * KD];    // [o][e][k*128+d]
__device__ __align__(16) __nv_bfloat16  g_wtlo[NOUT * DOUT * KD];
__device__ __align__(16) float          g_scale[YCOLS];
__device__ __align__(16) float          g_shift[YCOLS];
__device__ __align__(16) float          g_psum[NMT * YCOLS];         // 128 KB
__device__ __align__(16) float          g_psq [NMT * YCOLS];         // 128 KB

// ---------------- helpers ----------------
__device__ __forceinline__ uint32_t smem_u32(const void* p) {
    uint32_t a;
    asm("{ .reg .u64 t; cvta.to.shared.u64 t, %1; cvt.u32.u64 %0, t; }" : "=r"(a) : "l"(p));
    return a;
}
__device__ __forceinline__ void cp_async16(uint32_t dst, const void* src) {
    asm volatile("cp.async.cg.shared.global [%0], [%1], 16;" :: "r"(dst), "l"(src) : "memory");
}
__device__ __forceinline__ void cp_commit() {
    asm volatile("cp.async.commit_group;" ::: "memory");
}
template <int N>
__device__ __forceinline__ void cp_wait() {
    asm volatile("cp.async.wait_group %0;" :: "n"(N) : "memory");
}
__device__ __forceinline__ void ldsm_x4(uint32_t* r, uint32_t addr) {
    asm volatile("ldmatrix.sync.aligned.m8n8.x4.shared.b16 {%0,%1,%2,%3}, [%4];"
                 : "=r"(r[0]), "=r"(r[1]), "=r"(r[2]), "=r"(r[3]) : "r"(addr));
}
__device__ __forceinline__ void mma16816(float* d, const uint32_t* a, uint32_t b0, uint32_t b1) {
    asm volatile(
        "mma.sync.aligned.m16n8k16.row.col.f32.bf16.bf16.f32 "
        "{%0,%1,%2,%3}, {%4,%5,%6,%7}, {%8,%9}, {%0,%1,%2,%3};"
        : "+f"(d[0]), "+f"(d[1]), "+f"(d[2]), "+f"(d[3])
        : "r"(a[0]), "r"(a[1]), "r"(a[2]), "r"(a[3]), "r"(b0), "r"(b1));
}

// ---------------- kernel 1: fused prep (split x; split+transpose W) ----------------
__global__ void __launch_bounds__(256) eb_prep(const float* __restrict__ x,
                                               const float* __restrict__ W) {
    __shared__ float tile[128][33];
    if (blockIdx.x < 4096) {
        // ---- split x -> bf16 hi/lo ----
        int i = blockIdx.x * 256 + threadIdx.x;          // over 1,048,576 float4s
        float4 v = reinterpret_cast<const float4*>(x)[i];
        __nv_bfloat16 h0 = __float2bfloat16(v.x);
        __nv_bfloat16 h1 = __float2bfloat16(v.y);
        __nv_bfloat16 h2 = __float2bfloat16(v.z);
        __nv_bfloat16 h3 = __float2bfloat16(v.w);
        __nv_bfloat16 l0 = __float2bfloat16(v.x - __bfloat162float(h0));
        __nv_bfloat16 l1 = __float2bfloat16(v.y - __bfloat162float(h1));
        __nv_bfloat16 l2 = __float2bfloat16(v.z - __bfloat162float(h2));
        __nv_bfloat16 l3 = __float2bfloat16(v.w - __bfloat162float(h3));
        uint2 ph, pl;
        ph.x = (uint32_t)__bfloat16_as_ushort(h0) | ((uint32_t)__bfloat16_as_ushort(h1) << 16);
        ph.y = (uint32_t)__bfloat16_as_ushort(h2) | ((uint32_t)__bfloat16_as_ushort(h3) << 16);
        pl.x = (uint32_t)__bfloat16_as_ushort(l0) | ((uint32_t)__bfloat16_as_ushort(l1) << 16);
        pl.y = (uint32_t)__bfloat16_as_ushort(l2) | ((uint32_t)__bfloat16_as_ushort(l3) << 16);
        reinterpret_cast<uint2*>(g_xhi)[i] = ph;
        reinterpret_cast<uint2*>(g_xlo)[i] = pl;
    } else {
        // ---- split + transpose W -> Wt[o][e][k*128+d] ----
        int ok = blockIdx.x - 4096;    // (o,k) pair: 256 blocks
        int o = ok >> 2, k = ok & 3;
        const float* src = W + (size_t)ok * (DIN * DOUT);   // W[o][k][d][e]
        int t = threadIdx.x;
        for (int eb = 0; eb < 4; ++eb) {
            __syncthreads();
            #pragma unroll
            for (int it = 0; it < 16; ++it) {
                int flat = it * 256 + t;
                int d = flat >> 5, e2 = flat & 31;
                tile[d][e2] = src[d * DOUT + eb * 32 + e2];
            }
            __syncthreads();
            #pragma unroll
            for (int it = 0; it < 16; ++it) {
                int flat = it * 256 + t;
                int e2 = flat >> 7, d = flat & 127;
                float v = tile[d][e2];
                __nv_bfloat16 h = __float2bfloat16(v);
                __nv_bfloat16 l = __float2bfloat16(v - __bfloat162float(h));
                size_t off = (size_t)o * (DOUT * KD) + (size_t)(eb * 32 + e2) * KD + k * DIN + d;
                g_wthi[off] = h;
                g_wtlo[off] = l;
            }
        }
    }
}

// ---------------- kernel 2: HMMA GEMM + fused column stats ----------------
// Per CTA: D(128x128) += A(128 x 1536) * B(1536 x 128)^T  for one (o, m-tile).
// K streamed as 24 chunks of 64 bf16 (=128B rows). 3-stage cp.async pipeline.
// Epilogue additionally reduces per-column sum/sumsq over the 128-row tile
// into g_psum/g_psq (slot = mt), eliminating a separate 16.8MB stats pass.
#define STAGE_BYTES 32768
#define GEMM_SMEM_BYTES (3 * STAGE_BYTES + 1024)

__global__ void __launch_bounds__(256, 2)
eb_gemm(const int* __restrict__ idx) {
    extern __shared__ char dsm[];
    uint32_t raw = smem_u32(dsm);
    uint32_t sbase = (raw + 1023u) & ~1023u;
    char* sptr = dsm + (sbase - raw);

    const int tid  = threadIdx.x;
    const int lane = tid & 31;
    const int wid  = tid >> 5;
    const int warp_m = wid & 3;          // 4 M-warps of 32 rows
    const int warp_n = wid >> 2;         // 2 N-warps of 64 cols
    const int o  = blockIdx.x >> 2;
    const int mt = blockIdx.x & 3;

    int nin[4];
    #pragma unroll
    for (int k = 0; k < 4; ++k) nin[k] = idx[(o << 2) + k];

    auto prefetch = [&](int c) {
        int s = c >> 3, rm = c & 7, k = rm >> 1, dh = rm & 1;
        const __nv_bfloat16* asrc = (s == 2) ? g_xlo  : g_xhi;
        const __nv_bfloat16* bsrc = (s == 1) ? g_wtlo : g_wthi;
        uint32_t abuf = sbase + (uint32_t)(c % 3) * STAGE_BYTES;
        uint32_t bbuf = abuf + 16384;
        const __nv_bfloat16* abase = asrc + ((size_t)(mt * 128) * NIN + nin[k]) * DIN + dh * 64;
        const __nv_bfloat16* bbase = bsrc + (size_t)o * (DOUT * KD) + k * DIN + dh * 64;
        #pragma unroll
        for (int it = 0; it < 4; ++it) {
            int v = it * 256 + tid;          // 1024 16B chunks per tile
            int row = v >> 3, cc = v & 7;
            uint32_t dsw = (uint32_t)row * 128 + (((uint32_t)cc * 16) ^ (((uint32_t)row & 7) << 4));
            cp_async16(abuf + dsw, abase + (size_t)row * (NIN * DIN) + cc * 8);
            cp_async16(bbuf + dsw, bbase + (size_t)row * KD + cc * 8);
        }
    };

    const int sub = lane >> 3;
    const int rowA = warp_m * 32 + (sub & 1) * 8 + (lane & 7);
    const int khA  = sub >> 1;
    const uint32_t swzA = ((uint32_t)rowA & 7) << 4;
    const int rowB = warp_n * 64 + (sub >> 1) * 8 + (lane & 7);
    const int khB  = sub & 1;
    const uint32_t swzB = ((uint32_t)rowB & 7) << 4;

    float acc[2][8][4];
    #pragma unroll
    for (int mi = 0; mi < 2; ++mi)
        #pragma unroll
        for (int ni = 0; ni < 8; ++ni)
            #pragma unroll
            for (int q = 0; q < 4; ++q) acc[mi][ni][q] = 0.0f;

    prefetch(0); cp_commit();
    prefetch(1); cp_commit();

    for (int c = 0; c < NCHUNK; ++c) {
        cp_wait<1>();
        __syncthreads();
        if (c + 2 < NCHUNK) prefetch(c + 2);
        cp_commit();

        uint32_t abuf = sbase + (uint32_t)(c % 3) * STAGE_BYTES;
        uint32_t bbuf = abuf + 16384;
        #pragma unroll
        for (int ks = 0; ks < 4; ++ks) {
            uint32_t ka = (((uint32_t)ks * 32 + (uint32_t)khA * 16) ^ swzA);
            uint32_t kb = (((uint32_t)ks * 32 + (uint32_t)khB * 16) ^ swzB);
            uint32_t a[2][4];
            ldsm_x4(a[0], abuf + (uint32_t)rowA * 128 + ka);
            ldsm_x4(a[1], abuf + (uint32_t)(rowA + 16) * 128 + ka);
            uint32_t b[4][4];
            #pragma unroll
            for (int nb = 0; nb < 4; ++nb)
                ldsm_x4(b[nb], bbuf + (uint32_t)(rowB + nb * 16) * 128 + kb);
            #pragma unroll
            for (int mi = 0; mi < 2; ++mi)
                #pragma unroll
                for (int ni = 0; ni < 8; ++ni)
                    mma16816(acc[mi][ni], a[mi], b[ni >> 1][(ni & 1) * 2], b[ni >> 1][(ni & 1) * 2 + 1]);
        }
        __syncthreads();
    }

    // ---- epilogue 1: write fp32 tile to g_y ----
    const int r0 = mt * 128 + warp_m * 32 + (lane >> 2);
    const int col0 = o * DOUT + warp_n * 64 + (lane & 3) * 2;
    #pragma unroll
    for (int mi = 0; mi < 2; ++mi) {
        #pragma unroll
        for (int ni = 0; ni < 8; ++ni) {
            float* p0 = g_y + (size_t)(r0 + mi * 16) * YCOLS + col0 + ni * 8;
            float* p1 = p0 + 8 * YCOLS;
            *reinterpret_cast<float2*>(p0) = make_float2(acc[mi][ni][0], acc[mi][ni][1]);
            *reinterpret_cast<float2*>(p1) = make_float2(acc[mi][ni][2], acc[mi][ni][3]);
        }
    }

    // ---- epilogue 2: fused per-column sum/sumsq over this 128-row tile ----
    // Per-thread partials over its 4 rows per column (2 mi x 2 row-halves).
    float csum[8][2], csq[8][2];
    #pragma unroll
    for (int ni = 0; ni < 8; ++ni) {
        #pragma unroll
        for (int q = 0; q < 2; ++q) {
            float a0 = acc[0][ni][q],     a1 = acc[0][ni][q + 2];
            float a2 = acc[1][ni][q],     a3 = acc[1][ni][q + 2];
            csum[ni][q] = (a0 + a1) + (a2 + a3);
            csq [ni][q] = fmaf(a0, a0, fmaf(a1, a1, fmaf(a2, a2, a3 * a3)));
        }
    }
    // reduce across the 8 row-groups (lanes differing in bits [2:5))
    #pragma unroll
    for (int m = 4; m <= 16; m <<= 1) {
        #pragma unroll
        for (int ni = 0; ni < 8; ++ni) {
            #pragma unroll
            for (int q = 0; q < 2; ++q) {
                csum[ni][q] += __shfl_xor_sync(0xFFFFFFFFu, csum[ni][q], m);
                csq [ni][q] += __shfl_xor_sync(0xFFFFFFFFu, csq [ni][q], m);
            }
        }
    }
    // smem fold across the 4 warp_m bands (reuse stage-0 pipeline buffer)
    float* s_sum = reinterpret_cast<float*>(sptr);          // [4][128]
    float* s_sq  = s_sum + 512;                              // [4][128]
    __syncthreads();
    if ((lane >> 2) == 0) {
        int cbase = warp_n * 64 + (lane & 3) * 2;
        #pragma unroll
        for (int ni = 0; ni < 8; ++ni) {
            #pragma unroll
            for (int q = 0; q < 2; ++q) {
                s_sum[warp_m * 128 + cbase + ni * 8 + q] = csum[ni][q];
                s_sq [warp_m * 128 + cbase + ni * 8 + q] = csq [ni][q];
            }
        }
    }
    __syncthreads();
    if (tid < 128) {
        float ts = (s_sum[tid] + s_sum[128 + tid]) + (s_sum[256 + tid] + s_sum[384 + tid]);
        float tq = (s_sq [tid] + s_sq [128 + tid]) + (s_sq [256 + tid] + s_sq [384 + tid]);
        g_psum[mt * YCOLS + o * DOUT + tid] = ts;
        g_psq [mt * YCOLS + o * DOUT + tid] = tq;
    }
}

// ---------------- kernel 3: finalize scale/shift ----------------
__global__ void __launch_bounds__(256) eb_stats2(const float* __restrict__ gamma,
                                                 const float* __restrict__ beta) {
    int j = blockIdx.x * 256 + threadIdx.x;       // 8192 columns
    float sum = 0.f, sq = 0.f;
    #pragma unroll
    for (int s = 0; s < NMT; ++s) {
        sum += g_psum[s * YCOLS + j];
        sq  += g_psq [s * YCOLS + j];
    }
    float inv = 1.0f / (float)B_DIM;
    float mean = sum * inv;
    float var  = fmaf(sq, inv, -mean * mean);
    float sc = gamma[j] * rsqrtf(var + BN_EPS);
    g_scale[j] = sc;
    g_shift[j] = fmaf(-mean, sc, beta[j]);
}

// ---------------- kernel 4: BN apply + SiLU ----------------
__global__ void eb_bn_silu(float* __restrict__ out) {
    int i = blockIdx.x * blockDim.x + threadIdx.x;   // over 1,048,576 float4s
    float4 v = reinterpret_cast<const float4*>(g_y)[i];
    int col = (i << 2) & (YCOLS - 1);
    float4 sc = *reinterpret_cast<const float4*>(g_scale + col);
    float4 sh = *reinterpret_cast<const float4*>(g_shift + col);
    float y0 = fmaf(v.x, sc.x, sh.x);
    float y1 = fmaf(v.y, sc.y, sh.y);
    float y2 = fmaf(v.z, sc.z, sh.z);
    float y3 = fmaf(v.w, sc.w, sh.w);
    float4 r;
    r.x = y0 / (1.0f + expf(-y0));
    r.y = y1 / (1.0f + expf(-y1));
    r.z = y2 / (1.0f + expf(-y2));
    r.w = y3 / (1.0f + expf(-y3));
    reinterpret_cast<float4*>(out)[i] = r;
}

// ---------------- launch ----------------
extern "C" void kernel_launch(void* const* d_in, const int* in_sizes, int n_in,
                              void* d_out, int out_size) {
    const float* x     = (const float*)d_in[0];   // (512,64,128)
    const float* W     = (const float*)d_in[1];   // (64,4,128,128)
    // d_in[2] = bias: provably cancelled by BatchNorm (batch-constant shift) — unused.
    const float* gamma = (const float*)d_in[3];   // (8192)
    const float* beta  = (const float*)d_in[4];   // (8192)
    const int*   idx   = (const int*)d_in[5];     // (64,4)
    float* out = (float*)d_out;

    cudaFuncSetAttribute(eb_gemm, cudaFuncAttributeMaxDynamicSharedMemorySize, GEMM_SMEM_BYTES);

    eb_prep<<<4096 + 256, 256>>>(x, W);
    eb_gemm<<<256, 256, GEMM_SMEM_BYTES>>>(idx);
    eb_stats2<<<32, 256>>>(gamma, beta);
    eb_bn_silu<<<4096, 256>>>(out);
}

// round 5
// speedup vs baseline: 1.8013x; 1.8013x over previous
#include <cuda_runtime.h>
#include <cuda_fp16.h>
#include <cstdint>

// ---------------- problem dims ----------------
#define B_DIM 512
#define NIN   64
#define DIN   128
#define NOUT  64
#define DOUT  128
#define KSEL  4
#define YCOLS (NOUT * DOUT)        // 8192
#define YELEMS (B_DIM * YCOLS)     // 4194304
#define BN_EPS 1e-5f

#define KD      (KSEL * DIN)       // 512 (logical K per head)
#define NCHUNK  8                  // 4 k-sel x 2 half-DIN; 64 fp16 per chunk (single-pass fp16)

#define NROWG   16                 // row groups for two-phase stats
#define ROWS_PER_G (B_DIM / NROWG) // 32

// ---------------- scratch (device globals; no allocation allowed) ----------------
__device__ __align__(16) float   g_y[YELEMS];                 // 16.8 MB
__device__ __align__(16) __half  g_xh[B_DIM * NIN * DIN];     // 8.4 MB
__device__ __align__(16) __half  g_wt[NOUT * DOUT * KD];      // [o][e][k*128+d], 8.4 MB
__device__ __align__(16) float   g_scale[YCOLS];
__device__ __align__(16) float   g_shift[YCOLS];
__device__ __align__(16) float   g_psum[NROWG * YCOLS];       // 512 KB
__device__ __align__(16) float   g_psq [NROWG * YCOLS];       // 512 KB

// ---------------- helpers ----------------
__device__ __forceinline__ uint32_t smem_u32(const void* p) {
    uint32_t a;
    asm("{ .reg .u64 t; cvta.to.shared.u64 t, %1; cvt.u32.u64 %0, t; }" : "=r"(a) : "l"(p));
    return a;
}
__device__ __forceinline__ void cp_async16(uint32_t dst, const void* src) {
    asm volatile("cp.async.cg.shared.global [%0], [%1], 16;" :: "r"(dst), "l"(src) : "memory");
}
__device__ __forceinline__ void cp_commit() {
    asm volatile("cp.async.commit_group;" ::: "memory");
}
template <int N>
__device__ __forceinline__ void cp_wait() {
    asm volatile("cp.async.wait_group %0;" :: "n"(N) : "memory");
}
__device__ __forceinline__ void ldsm_x4(uint32_t* r, uint32_t addr) {
    asm volatile("ldmatrix.sync.aligned.m8n8.x4.shared.b16 {%0,%1,%2,%3}, [%4];"
                 : "=r"(r[0]), "=r"(r[1]), "=r"(r[2]), "=r"(r[3]) : "r"(addr));
}
__device__ __forceinline__ void mma16816(float* d, const uint32_t* a, uint32_t b0, uint32_t b1) {
    asm volatile(
        "mma.sync.aligned.m16n8k16.row.col.f32.f16.f16.f32 "
        "{%0,%1,%2,%3}, {%4,%5,%6,%7}, {%8,%9}, {%0,%1,%2,%3};"
        : "+f"(d[0]), "+f"(d[1]), "+f"(d[2]), "+f"(d[3])
        : "r"(a[0]), "r"(a[1]), "r"(a[2]), "r"(a[3]), "r"(b0), "r"(b1));
}

// ---------------- kernel 1: convert x -> fp16 ----------------
__global__ void __launch_bounds__(256) eb_conv_x(const float* __restrict__ x) {
    int i = blockIdx.x * 256 + threadIdx.x;          // over 1,048,576 float4s
    float4 v = reinterpret_cast<const float4*>(x)[i];
    __half2 p0 = __floats2half2_rn(v.x, v.y);
    __half2 p1 = __floats2half2_rn(v.z, v.w);
    uint2 pk;
    pk.x = *reinterpret_cast<uint32_t*>(&p0);
    pk.y = *reinterpret_cast<uint32_t*>(&p1);
    reinterpret_cast<uint2*>(g_xh)[i] = pk;
}

// ---------------- kernel 2: convert + transpose W -> Wt[o][e][k*128+d] fp16 ----------------
__global__ void __launch_bounds__(256) eb_conv_w(const float* __restrict__ W) {
    __shared__ float tile[128][33];
    int ok = blockIdx.x;           // (o,k) pair: 256 blocks
    int o = ok >> 2, k = ok & 3;
    const float* src = W + (size_t)ok * (DIN * DOUT);   // W[o][k][d][e]
    int t = threadIdx.x;
    for (int eb = 0; eb < 4; ++eb) {
        __syncthreads();
        #pragma unroll
        for (int it = 0; it < 16; ++it) {
            int flat = it * 256 + t;
            int d = flat >> 5, e2 = flat & 31;
            tile[d][e2] = src[d * DOUT + eb * 32 + e2];
        }
        __syncthreads();
        #pragma unroll
        for (int it = 0; it < 16; ++it) {
            int flat = it * 256 + t;
            int e2 = flat >> 7, d = flat & 127;
            float v = tile[d][e2];
            size_t off = (size_t)o * (DOUT * KD) + (size_t)(eb * 32 + e2) * KD + k * DIN + d;
            g_wt[off] = __float2half_rn(v);
        }
    }
}

// ---------------- kernel 3: HMMA GEMM (fp16 single-pass) ----------------
// Per CTA: D(128x128) = A(128 x 512) * B(512 x 128)^T  for one (o, m-tile).
// K streamed as 8 chunks of 64 fp16 (=128B rows). 3-stage cp.async pipeline.
#define STAGE_BYTES 32768
#define GEMM_SMEM_BYTES (3 * STAGE_BYTES + 1024)

__global__ void __launch_bounds__(256, 2)
eb_gemm(const int* __restrict__ idx) {
    extern __shared__ char dsm[];
    uint32_t raw = smem_u32(dsm);
    uint32_t sbase = (raw + 1023u) & ~1023u;

    const int tid  = threadIdx.x;
    const int lane = tid & 31;
    const int wid  = tid >> 5;
    const int warp_m = wid & 3;          // 4 M-warps of 32 rows
    const int warp_n = wid >> 2;         // 2 N-warps of 64 cols
    const int o  = blockIdx.x >> 2;
    const int mt = blockIdx.x & 3;

    int nin[4];
    #pragma unroll
    for (int k = 0; k < 4; ++k) nin[k] = idx[(o << 2) + k];

    auto prefetch = [&](int c) {
        int k = c >> 1, dh = c & 1;
        uint32_t abuf = sbase + (uint32_t)(c % 3) * STAGE_BYTES;
        uint32_t bbuf = abuf + 16384;
        const __half* abase = g_xh + ((size_t)(mt * 128) * NIN + nin[k]) * DIN + dh * 64;
        const __half* bbase = g_wt + (size_t)o * (DOUT * KD) + k * DIN + dh * 64;
        #pragma unroll
        for (int it = 0; it < 4; ++it) {
            int v = it * 256 + tid;          // 1024 16B chunks per tile
            int row = v >> 3, cc = v & 7;
            uint32_t dsw = (uint32_t)row * 128 + (((uint32_t)cc * 16) ^ (((uint32_t)row & 7) << 4));
            cp_async16(abuf + dsw, abase + (size_t)row * (NIN * DIN) + cc * 8);
            cp_async16(bbuf + dsw, bbase + (size_t)row * KD + cc * 8);
        }
    };

    const int sub = lane >> 3;
    const int rowA = warp_m * 32 + (sub & 1) * 8 + (lane & 7);
    const int khA  = sub >> 1;
    const uint32_t swzA = ((uint32_t)rowA & 7) << 4;
    const int rowB = warp_n * 64 + (sub >> 1) * 8 + (lane & 7);
    const int khB  = sub & 1;
    const uint32_t swzB = ((uint32_t)rowB & 7) << 4;

    float acc[2][8][4];
    #pragma unroll
    for (int mi = 0; mi < 2; ++mi)
        #pragma unroll
        for (int ni = 0; ni < 8; ++ni)
            #pragma unroll
            for (int q = 0; q < 4; ++q) acc[mi][ni][q] = 0.0f;

    prefetch(0); cp_commit();
    prefetch(1); cp_commit();

    for (int c = 0; c < NCHUNK; ++c) {
        cp_wait<1>();
        __syncthreads();
        if (c + 2 < NCHUNK) prefetch(c + 2);
        cp_commit();

        uint32_t abuf = sbase + (uint32_t)(c % 3) * STAGE_BYTES;
        uint32_t bbuf = abuf + 16384;
        #pragma unroll
        for (int ks = 0; ks < 4; ++ks) {
            uint32_t ka = (((uint32_t)ks * 32 + (uint32_t)khA * 16) ^ swzA);
            uint32_t kb = (((uint32_t)ks * 32 + (uint32_t)khB * 16) ^ swzB);
            uint32_t a[2][4];
            ldsm_x4(a[0], abuf + (uint32_t)rowA * 128 + ka);
            ldsm_x4(a[1], abuf + (uint32_t)(rowA + 16) * 128 + ka);
            uint32_t b[4][4];
            #pragma unroll
            for (int nb = 0; nb < 4; ++nb)
                ldsm_x4(b[nb], bbuf + (uint32_t)(rowB + nb * 16) * 128 + kb);
            #pragma unroll
            for (int mi = 0; mi < 2; ++mi)
                #pragma unroll
                for (int ni = 0; ni < 8; ++ni)
                    mma16816(acc[mi][ni], a[mi], b[ni >> 1][(ni & 1) * 2], b[ni >> 1][(ni & 1) * 2 + 1]);
        }
        __syncthreads();
    }

    const int r0 = mt * 128 + warp_m * 32 + (lane >> 2);
    const int col0 = o * DOUT + warp_n * 64 + (lane & 3) * 2;
    #pragma unroll
    for (int mi = 0; mi < 2; ++mi) {
        #pragma unroll
        for (int ni = 0; ni < 8; ++ni) {
            float* p0 = g_y + (size_t)(r0 + mi * 16) * YCOLS + col0 + ni * 8;
            float* p1 = p0 + 8 * YCOLS;
            *reinterpret_cast<float2*>(p0) = make_float2(acc[mi][ni][0], acc[mi][ni][1]);
            *reinterpret_cast<float2*>(p1) = make_float2(acc[mi][ni][2], acc[mi][ni][3]);
        }
    }
}

// ---------------- kernel 4a: partial per-column sums (row-group parallel) ----------------
__global__ void __launch_bounds__(256) eb_stats1() {
    int j  = blockIdx.x * 256 + threadIdx.x;      // column
    int rg = blockIdx.y;                          // row group
    const float* p = g_y + (size_t)rg * ROWS_PER_G * YCOLS + j;
    float s0 = 0.f, s1 = 0.f, s2 = 0.f, s3 = 0.f;
    float q0 = 0.f, q1 = 0.f, q2 = 0.f, q3 = 0.f;
    #pragma unroll
    for (int r = 0; r < ROWS_PER_G; r += 4) {
        float a0 = p[(r + 0) * YCOLS];
        float a1 = p[(r + 1) * YCOLS];
        float a2 = p[(r + 2) * YCOLS];
        float a3 = p[(r + 3) * YCOLS];
        s0 += a0; q0 = fmaf(a0, a0, q0);
        s1 += a1; q1 = fmaf(a1, a1, q1);
        s2 += a2; q2 = fmaf(a2, a2, q2);
        s3 += a3; q3 = fmaf(a3, a3, q3);
    }
    g_psum[rg * YCOLS + j] = (s0 + s1) + (s2 + s3);
    g_psq [rg * YCOLS + j] = (q0 + q1) + (q2 + q3);
}

// ---------------- kernel 4b: finalize scale/shift ----------------
__global__ void __launch_bounds__(256) eb_stats2(const float* __restrict__ gamma,
                                                 const float* __restrict__ beta) {
    int j = blockIdx.x * 256 + threadIdx.x;       // 8192 columns
    float sum = 0.f, sq = 0.f;
    #pragma unroll
    for (int rg = 0; rg < NROWG; ++rg) {
        sum += g_psum[rg * YCOLS + j];
        sq  += g_psq [rg * YCOLS + j];
    }
    float inv = 1.0f / (float)B_DIM;
    float mean = sum * inv;
    float var  = fmaf(sq, inv, -mean * mean);
    float sc = gamma[j] * rsqrtf(var + BN_EPS);
    g_scale[j] = sc;
    g_shift[j] = fmaf(-mean, sc, beta[j]);
}

// ---------------- kernel 5: BN apply + SiLU ----------------
__global__ void __launch_bounds__(256) eb_bn_silu(float* __restrict__ out) {
    int i = blockIdx.x * 256 + threadIdx.x;          // over 1,048,576 float4s
    float4 v = reinterpret_cast<const float4*>(g_y)[i];
    int col = (i << 2) & (YCOLS - 1);
    float4 sc = *reinterpret_cast<const float4*>(g_scale + col);
    float4 sh = *reinterpret_cast<const float4*>(g_shift + col);
    float y0 = fmaf(v.x, sc.x, sh.x);
    float y1 = fmaf(v.y, sc.y, sh.y);
    float y2 = fmaf(v.z, sc.z, sh.z);
    float y3 = fmaf(v.w, sc.w, sh.w);
    float4 r;
    r.x = y0 * __frcp_rn(1.0f + __expf(-y0));
    r.y = y1 * __frcp_rn(1.0f + __expf(-y1));
    r.z = y2 * __frcp_rn(1.0f + __expf(-y2));
    r.w = y3 * __frcp_rn(1.0f + __expf(-y3));
    reinterpret_cast<float4*>(out)[i] = r;
}

// ---------------- launch ----------------
extern "C" void kernel_launch(void* const* d_in, const int* in_sizes, int n_in,
                              void* d_out, int out_size) {
    const float* x     = (const float*)d_in[0];   // (512,64,128)
    const float* W     = (const float*)d_in[1];   // (64,4,128,128)
    // d_in[2] = bias: provably cancelled by BatchNorm (batch-constant shift) — unused.
    const float* gamma = (const float*)d_in[3];   // (8192)
    const float* beta  = (const float*)d_in[4];   // (8192)
    const int*   idx   = (const int*)d_in[5];     // (64,4)
    float* out = (float*)d_out;

    cudaFuncSetAttribute(eb_gemm, cudaFuncAttributeMaxDynamicSharedMemorySize, GEMM_SMEM_BYTES);

    eb_conv_x<<<4096, 256>>>(x);
    eb_conv_w<<<256, 256>>>(W);
    eb_gemm<<<256, 256, GEMM_SMEM_BYTES>>>(idx);
    eb_stats1<<<dim3(32, NROWG), 256>>>();
    eb_stats2<<<32, 256>>>(gamma, beta);
    eb_bn_silu<<<4096, 256>>>(out);
}

// round 6
// speedup vs baseline: 1.9758x; 1.0969x over previous
#include <cuda_runtime.h>
#include <cuda_fp16.h>
#include <cstdint>

// ---------------- problem dims ----------------
#define B_DIM 512
#define NIN   64
#define DIN   128
#define NOUT  64
#define DOUT  128
#define KSEL  4
#define YCOLS (NOUT * DOUT)        // 8192
#define YELEMS (B_DIM * YCOLS)     // 4194304
#define BN_EPS 1e-5f

#define KD      (KSEL * DIN)       // 512 (logical K per head)
#define NCHUNK  8                  // 4 k-sel x 2 half-DIN; 64 fp16 per chunk (single-pass fp16)
#define NMT     4                  // M-tiles per head (partial-stats slots)

// ---------------- scratch (device globals; no allocation allowed) ----------------
__device__ __align__(16) float   g_y[YELEMS];                 // 16.8 MB
__device__ __align__(16) __half  g_xh[B_DIM * NIN * DIN];     // 8.4 MB
__device__ __align__(16) __half  g_wt[NOUT * DOUT * KD];      // [o][e][k*128+d], 8.4 MB
__device__ __align__(16) float   g_scale[YCOLS];
__device__ __align__(16) float   g_shift[YCOLS];
__device__ __align__(16) float   g_psum[NMT * YCOLS];         // 128 KB
__device__ __align__(16) float   g_psq [NMT * YCOLS];         // 128 KB

// ---------------- helpers ----------------
__device__ __forceinline__ uint32_t smem_u32(const void* p) {
    uint32_t a;
    asm("{ .reg .u64 t; cvta.to.shared.u64 t, %1; cvt.u32.u64 %0, t; }" : "=r"(a) : "l"(p));
    return a;
}
__device__ __forceinline__ void cp_async16(uint32_t dst, const void* src) {
    asm volatile("cp.async.cg.shared.global [%0], [%1], 16;" :: "r"(dst), "l"(src) : "memory");
}
__device__ __forceinline__ void cp_commit() {
    asm volatile("cp.async.commit_group;" ::: "memory");
}
template <int N>
__device__ __forceinline__ void cp_wait() {
    asm volatile("cp.async.wait_group %0;" :: "n"(N) : "memory");
}
__device__ __forceinline__ void ldsm_x4(uint32_t* r, uint32_t addr) {
    asm volatile("ldmatrix.sync.aligned.m8n8.x4.shared.b16 {%0,%1,%2,%3}, [%4];"
                 : "=r"(r[0]), "=r"(r[1]), "=r"(r[2]), "=r"(r[3]) : "r"(addr));
}
__device__ __forceinline__ void mma16816(float* d, const uint32_t* a, uint32_t b0, uint32_t b1) {
    asm volatile(
        "mma.sync.aligned.m16n8k16.row.col.f32.f16.f16.f32 "
        "{%0,%1,%2,%3}, {%4,%5,%6,%7}, {%8,%9}, {%0,%1,%2,%3};"
        : "+f"(d[0]), "+f"(d[1]), "+f"(d[2]), "+f"(d[3])
        : "r"(a[0]), "r"(a[1]), "r"(a[2]), "r"(a[3]), "r"(b0), "r"(b1));
}
__device__ __forceinline__ float rcp_fast(float x) {
    float r;
    asm("rcp.approx.f32 %0, %1;" : "=f"(r) : "f"(x));
    return r;
}

// ---------------- kernel 1: convert x -> fp16 ----------------
__global__ void __launch_bounds__(256) eb_conv_x(const float* __restrict__ x) {
    int i = blockIdx.x * 256 + threadIdx.x;          // over 1,048,576 float4s
    float4 v = reinterpret_cast<const float4*>(x)[i];
    __half2 p0 = __floats2half2_rn(v.x, v.y);
    __half2 p1 = __floats2half2_rn(v.z, v.w);
    uint2 pk;
    pk.x = *reinterpret_cast<uint32_t*>(&p0);
    pk.y = *reinterpret_cast<uint32_t*>(&p1);
    reinterpret_cast<uint2*>(g_xh)[i] = pk;
}

// ---------------- kernel 2: convert + transpose W -> Wt[o][e][k*128+d] fp16 ----------------
__global__ void __launch_bounds__(256) eb_conv_w(const float* __restrict__ W) {
    __shared__ float tile[128][33];
    int ok = blockIdx.x;           // (o,k) pair: 256 blocks
    int o = ok >> 2, k = ok & 3;
    const float* src = W + (size_t)ok * (DIN * DOUT);   // W[o][k][d][e]
    int t = threadIdx.x;
    for (int eb = 0; eb < 4; ++eb) {
        __syncthreads();
        #pragma unroll
        for (int it = 0; it < 16; ++it) {
            int flat = it * 256 + t;
            int d = flat >> 5, e2 = flat & 31;
            tile[d][e2] = src[d * DOUT + eb * 32 + e2];
        }
        __syncthreads();
        #pragma unroll
        for (int it = 0; it < 16; ++it) {
            int flat = it * 256 + t;
            int e2 = flat >> 7, d = flat & 127;
            float v = tile[d][e2];
            size_t off = (size_t)o * (DOUT * KD) + (size_t)(eb * 32 + e2) * KD + k * DIN + d;
            g_wt[off] = __float2half_rn(v);
        }
    }
}

// ---------------- kernel 3: HMMA GEMM (fp16) + fused column stats ----------------
// Per CTA: D(128x128) = A(128 x 512) * B(512 x 128)^T  for one (o, m-tile).
// Epilogue reduces per-column sum/sumsq over the 128-row tile into
// g_psum/g_psq (slot = mt), eliminating a separate 16.8MB stats pass.
#define STAGE_BYTES 32768
#define GEMM_SMEM_BYTES (3 * STAGE_BYTES + 1024)

__global__ void __launch_bounds__(256, 2)
eb_gemm(const int* __restrict__ idx) {
    extern __shared__ char dsm[];
    uint32_t raw = smem_u32(dsm);
    uint32_t sbase = (raw + 1023u) & ~1023u;
    char* sptr = dsm + (sbase - raw);

    const int tid  = threadIdx.x;
    const int lane = tid & 31;
    const int wid  = tid >> 5;
    const int warp_m = wid & 3;          // 4 M-warps of 32 rows
    const int warp_n = wid >> 2;         // 2 N-warps of 64 cols
    const int o  = blockIdx.x >> 2;
    const int mt = blockIdx.x & 3;

    int nin[4];
    #pragma unroll
    for (int k = 0; k < 4; ++k) nin[k] = idx[(o << 2) + k];

    auto prefetch = [&](int c) {
        int k = c >> 1, dh = c & 1;
        uint32_t abuf = sbase + (uint32_t)(c % 3) * STAGE_BYTES;
        uint32_t bbuf = abuf + 16384;
        const __half* abase = g_xh + ((size_t)(mt * 128) * NIN + nin[k]) * DIN + dh * 64;
        const __half* bbase = g_wt + (size_t)o * (DOUT * KD) + k * DIN + dh * 64;
        #pragma unroll
        for (int it = 0; it < 4; ++it) {
            int v = it * 256 + tid;          // 1024 16B chunks per tile
            int row = v >> 3, cc = v & 7;
            uint32_t dsw = (uint32_t)row * 128 + (((uint32_t)cc * 16) ^ (((uint32_t)row & 7) << 4));
            cp_async16(abuf + dsw, abase + (size_t)row * (NIN * DIN) + cc * 8);
            cp_async16(bbuf + dsw, bbase + (size_t)row * KD + cc * 8);
        }
    };

    const int sub = lane >> 3;
    const int rowA = warp_m * 32 + (sub & 1) * 8 + (lane & 7);
    const int khA  = sub >> 1;
    const uint32_t swzA = ((uint32_t)rowA & 7) << 4;
    const int rowB = warp_n * 64 + (sub >> 1) * 8 + (lane & 7);
    const int khB  = sub & 1;
    const uint32_t swzB = ((uint32_t)rowB & 7) << 4;

    float acc[2][8][4];
    #pragma unroll
    for (int mi = 0; mi < 2; ++mi)
        #pragma unroll
        for (int ni = 0; ni < 8; ++ni)
            #pragma unroll
            for (int q = 0; q < 4; ++q) acc[mi][ni][q] = 0.0f;

    prefetch(0); cp_commit();
    prefetch(1); cp_commit();

    for (int c = 0; c < NCHUNK; ++c) {
        cp_wait<1>();
        __syncthreads();
        if (c + 2 < NCHUNK) prefetch(c + 2);
        cp_commit();

        uint32_t abuf = sbase + (uint32_t)(c % 3) * STAGE_BYTES;
        uint32_t bbuf = abuf + 16384;
        #pragma unroll
        for (int ks = 0; ks < 4; ++ks) {
            uint32_t ka = (((uint32_t)ks * 32 + (uint32_t)khA * 16) ^ swzA);
            uint32_t kb = (((uint32_t)ks * 32 + (uint32_t)khB * 16) ^ swzB);
            uint32_t a[2][4];
            ldsm_x4(a[0], abuf + (uint32_t)rowA * 128 + ka);
            ldsm_x4(a[1], abuf + (uint32_t)(rowA + 16) * 128 + ka);
            uint32_t b[4][4];
            #pragma unroll
            for (int nb = 0; nb < 4; ++nb)
                ldsm_x4(b[nb], bbuf + (uint32_t)(rowB + nb * 16) * 128 + kb);
            #pragma unroll
            for (int mi = 0; mi < 2; ++mi)
                #pragma unroll
                for (int ni = 0; ni < 8; ++ni)
                    mma16816(acc[mi][ni], a[mi], b[ni >> 1][(ni & 1) * 2], b[ni >> 1][(ni & 1) * 2 + 1]);
        }
        __syncthreads();
    }

    // ---- epilogue 1: write fp32 tile to g_y ----
    const int r0 = mt * 128 + warp_m * 32 + (lane >> 2);
    const int col0 = o * DOUT + warp_n * 64 + (lane & 3) * 2;
    #pragma unroll
    for (int mi = 0; mi < 2; ++mi) {
        #pragma unroll
        for (int ni = 0; ni < 8; ++ni) {
            float* p0 = g_y + (size_t)(r0 + mi * 16) * YCOLS + col0 + ni * 8;
            float* p1 = p0 + 8 * YCOLS;
            *reinterpret_cast<float2*>(p0) = make_float2(acc[mi][ni][0], acc[mi][ni][1]);
            *reinterpret_cast<float2*>(p1) = make_float2(acc[mi][ni][2], acc[mi][ni][3]);
        }
    }

    // ---- epilogue 2: fused per-column sum/sumsq over this 128-row tile ----
    float csum[8][2], csq[8][2];
    #pragma unroll
    for (int ni = 0; ni < 8; ++ni) {
        #pragma unroll
        for (int q = 0; q < 2; ++q) {
            float a0 = acc[0][ni][q],     a1 = acc[0][ni][q + 2];
            float a2 = acc[1][ni][q],     a3 = acc[1][ni][q + 2];
            csum[ni][q] = (a0 + a1) + (a2 + a3);
            csq [ni][q] = fmaf(a0, a0, fmaf(a1, a1, fmaf(a2, a2, a3 * a3)));
        }
    }
    // reduce across the 8 row-groups within the warp (lanes differing in bits [2:5))
    #pragma unroll
    for (int m = 4; m <= 16; m <<= 1) {
        #pragma unroll
        for (int ni = 0; ni < 8; ++ni) {
            #pragma unroll
            for (int q = 0; q < 2; ++q) {
                csum[ni][q] += __shfl_xor_sync(0xFFFFFFFFu, csum[ni][q], m);
                csq [ni][q] += __shfl_xor_sync(0xFFFFFFFFu, csq [ni][q], m);
            }
        }
    }
    // smem fold across the 4 warp_m bands (reuse pipeline buffer)
    float* s_sum = reinterpret_cast<float*>(sptr);          // [4][128]
    float* s_sq  = s_sum + 512;                              // [4][128]
    __syncthreads();
    if ((lane >> 2) == 0) {
        int cbase = warp_n * 64 + (lane & 3) * 2;
        #pragma unroll
        for (int ni = 0; ni < 8; ++ni) {
            #pragma unroll
            for (int q = 0; q < 2; ++q) {
                s_sum[warp_m * 128 + cbase + ni * 8 + q] = csum[ni][q];
                s_sq [warp_m * 128 + cbase + ni * 8 + q] = csq [ni][q];
            }
        }
    }
    __syncthreads();
    if (tid < 128) {
        float ts = (s_sum[tid] + s_sum[128 + tid]) + (s_sum[256 + tid] + s_sum[384 + tid]);
        float tq = (s_sq [tid] + s_sq [128 + tid]) + (s_sq [256 + tid] + s_sq [384 + tid]);
        g_psum[mt * YCOLS + o * DOUT + tid] = ts;
        g_psq [mt * YCOLS + o * DOUT + tid] = tq;
    }
}

// ---------------- kernel 4: finalize scale/shift ----------------
__global__ void __launch_bounds__(256) eb_stats2(const float* __restrict__ gamma,
                                                 const float* __restrict__ beta) {
    int j = blockIdx.x * 256 + threadIdx.x;       // 8192 columns
    float sum = 0.f, sq = 0.f;
    #pragma unroll
    for (int s = 0; s < NMT; ++s) {
        sum += g_psum[s * YCOLS + j];
        sq  += g_psq [s * YCOLS + j];
    }
    float inv = 1.0f / (float)B_DIM;
    float mean = sum * inv;
    float var  = fmaf(sq, inv, -mean * mean);
    float sc = gamma[j] * rsqrtf(var + BN_EPS);
    g_scale[j] = sc;
    g_shift[j] = fmaf(-mean, sc, beta[j]);
}

// ---------------- kernel 5: BN apply + SiLU ----------------
__global__ void __launch_bounds__(256) eb_bn_silu(float* __restrict__ out) {
    int i = blockIdx.x * 256 + threadIdx.x;          // over 1,048,576 float4s
    float4 v = reinterpret_cast<const float4*>(g_y)[i];
    int col = (i << 2) & (YCOLS - 1);
    float4 sc = *reinterpret_cast<const float4*>(g_scale + col);
    float4 sh = *reinterpret_cast<const float4*>(g_shift + col);
    float y0 = fmaf(v.x, sc.x, sh.x);
    float y1 = fmaf(v.y, sc.y, sh.y);
    float y2 = fmaf(v.z, sc.z, sh.z);
    float y3 = fmaf(v.w, sc.w, sh.w);
    float4 r;
    r.x = y0 * rcp_fast(1.0f + __expf(-y0));
    r.y = y1 * rcp_fast(1.0f + __expf(-y1));
    r.z = y2 * rcp_fast(1.0f + __expf(-y2));
    r.w = y3 * rcp_fast(1.0f + __expf(-y3));
    reinterpret_cast<float4*>(out)[i] = r;
}

// ---------------- launch ----------------
extern "C" void kernel_launch(void* const* d_in, const int* in_sizes, int n_in,
                              void* d_out, int out_size) {
    const float* x     = (const float*)d_in[0];   // (512,64,128)
    const float* W     = (const float*)d_in[1];   // (64,4,128,128)
    // d_in[2] = bias: provably cancelled by BatchNorm (batch-constant shift) — unused.
    const float* gamma = (const float*)d_in[3];   // (8192)
    const float* beta  = (const float*)d_in[4];   // (8192)
    const int*   idx   = (const int*)d_in[5];     // (64,4)
    float* out = (float*)d_out;

    cudaFuncSetAttribute(eb_gemm, cudaFuncAttributeMaxDynamicSharedMemorySize, GEMM_SMEM_BYTES);

    eb_conv_x<<<4096, 256>>>(x);
    eb_conv_w<<<256, 256>>>(W);
    eb_gemm<<<256, 256, GEMM_SMEM_BYTES>>>(idx);
    eb_stats2<<<32, 256>>>(gamma, beta);
    eb_bn_silu<<<4096, 256>>>(out);
}

// round 7
// speedup vs baseline: 2.0870x; 1.0563x over previous
#include <cuda_runtime.h>
#include <cuda_fp16.h>
#include <cstdint>

// ---------------- problem dims ----------------
#define B_DIM 512
#define NIN   64
#define DIN   128
#define NOUT  64
#define DOUT  128
#define KSEL  4
#define YCOLS (NOUT * DOUT)        // 8192
#define YELEMS (B_DIM * YCOLS)     // 4194304
#define BN_EPS 1e-5f

#define KD      (KSEL * DIN)       // 512 (logical K per head)
#define NCHUNK  8                  // 4 k-sel x 2 half-DIN; 64 fp16 per chunk
#define NMT     4                  // M-tiles per head (partial-stats slots)
#define NCTA    256                // mega-kernel grid (all co-resident: 2/SM x 148 SMs = 296 max)

// ---------------- scratch (device globals; no allocation allowed) ----------------
__device__ __align__(16) float   g_y[YELEMS];                 // 16.8 MB
__device__ __align__(16) __half  g_xh[B_DIM * NIN * DIN];     // 8.4 MB
__device__ __align__(16) __half  g_wt[NOUT * DOUT * KD];      // [o][e][k*128+d], 8.4 MB
__device__ __align__(16) float   g_scale[YCOLS];
__device__ __align__(16) float   g_shift[YCOLS];
__device__ __align__(16) float   g_psum[NMT * YCOLS];         // 128 KB
__device__ __align__(16) float   g_psq [NMT * YCOLS];         // 128 KB
__device__ unsigned int          g_bar[4];                    // monotonic ticket barriers

// ---------------- helpers ----------------
__device__ __forceinline__ uint32_t smem_u32(const void* p) {
    uint32_t a;
    asm("{ .reg .u64 t; cvta.to.shared.u64 t, %1; cvt.u32.u64 %0, t; }" : "=r"(a) : "l"(p));
    return a;
}
__device__ __forceinline__ void cp_async16(uint32_t dst, const void* src) {
    asm volatile("cp.async.cg.shared.global [%0], [%1], 16;" :: "r"(dst), "l"(src) : "memory");
}
__device__ __forceinline__ void cp_commit() {
    asm volatile("cp.async.commit_group;" ::: "memory");
}
template <int N>
__device__ __forceinline__ void cp_wait() {
    asm volatile("cp.async.wait_group %0;" :: "n"(N) : "memory");
}
__device__ __forceinline__ void ldsm_x4(uint32_t* r, uint32_t addr) {
    asm volatile("ldmatrix.sync.aligned.m8n8.x4.shared.b16 {%0,%1,%2,%3}, [%4];"
                 : "=r"(r[0]), "=r"(r[1]), "=r"(r[2]), "=r"(r[3]) : "r"(addr));
}
__device__ __forceinline__ void mma16816(float* d, const uint32_t* a, uint32_t b0, uint32_t b1) {
    asm volatile(
        "mma.sync.aligned.m16n8k16.row.col.f32.f16.f16.f32 "
        "{%0,%1,%2,%3}, {%4,%5,%6,%7}, {%8,%9}, {%0,%1,%2,%3};"
        : "+f"(d[0]), "+f"(d[1]), "+f"(d[2]), "+f"(d[3])
        : "r"(a[0]), "r"(a[1]), "r"(a[2]), "r"(a[3]), "r"(b0), "r"(b1));
}
__device__ __forceinline__ float rcp_fast(float x) {
    float r;
    asm("rcp.approx.f32 %0, %1;" : "=f"(r) : "f"(x));
    return r;
}

// Grid-wide barrier: monotonic ticket counter, no reset needed (replay-safe).
// All NCTA CTAs are guaranteed co-resident (one wave), so spinning is deadlock-free.
__device__ __forceinline__ void grid_barrier(int slot) {
    __syncthreads();                       // all block threads' writes done
    if (threadIdx.x == 0) {
        __threadfence();                   // release (cumulative, gpu scope)
        unsigned ticket = atomicAdd(&g_bar[slot], 1u);
        unsigned target = (ticket / NCTA + 1u) * NCTA;
        unsigned v;
        do {
            asm volatile("ld.acquire.gpu.u32 %0, [%1];"
                         : "=r"(v) : "l"(&g_bar[slot]));
        } while ((int)(v - target) < 0);
    }
    __syncthreads();                       // broadcast acquire to the block
}

// ---------------- THE mega kernel ----------------
// Phases: [conv x + conv/transpose W] -> bar -> [GEMM + fused col-stats]
//         -> bar -> [finalize scale/shift] -> bar -> [BN apply + SiLU]
#define STAGE_BYTES 32768
#define GEMM_SMEM_BYTES (3 * STAGE_BYTES + 1024)

__global__ void __launch_bounds__(256, 2)
eb_mega(const float* __restrict__ x, const float* __restrict__ W,
        const float* __restrict__ gamma, const float* __restrict__ beta,
        const int* __restrict__ idx, float* __restrict__ out) {
    extern __shared__ char dsm[];
    uint32_t raw = smem_u32(dsm);
    uint32_t sbase = (raw + 1023u) & ~1023u;
    char* sptr = dsm + (sbase - raw);

    const int tid  = threadIdx.x;
    const int bid  = blockIdx.x;

    // ================= phase 0: convert inputs =================
    {
        // x -> fp16: 1,048,576 float4s / 256 CTAs = 4096 each
        const float4* xin = reinterpret_cast<const float4*>(x);
        #pragma unroll 4
        for (int it = 0; it < 16; ++it) {
            int i = bid * 4096 + it * 256 + tid;
            float4 v = xin[i];
            __half2 p0 = __floats2half2_rn(v.x, v.y);
            __half2 p1 = __floats2half2_rn(v.z, v.w);
            uint2 pk;
            pk.x = *reinterpret_cast<uint32_t*>(&p0);
            pk.y = *reinterpret_cast<uint32_t*>(&p1);
            reinterpret_cast<uint2*>(g_xh)[i] = pk;
        }
        // W (o,k) pair = bid: transpose 128x128 via smem (reuse pipeline buffer)
        float* tile = reinterpret_cast<float*>(sptr);   // [128][33]
        int o = bid >> 2, k = bid & 3;
        const float* src = W + (size_t)bid * (DIN * DOUT);   // W[o][k][d][e]
        for (int eb = 0; eb < 4; ++eb) {
            __syncthreads();
            #pragma unroll
            for (int it = 0; it < 16; ++it) {
                int flat = it * 256 + tid;
                int d = flat >> 5, e2 = flat & 31;
                tile[d * 33 + e2] = src[d * DOUT + eb * 32 + e2];
            }
            __syncthreads();
            #pragma unroll
            for (int it = 0; it < 16; ++it) {
                int flat = it * 256 + tid;
                int e2 = flat >> 7, d = flat & 127;
                float v = tile[d * 33 + e2];
                size_t off = (size_t)o * (DOUT * KD) + (size_t)(eb * 32 + e2) * KD + k * DIN + d;
                g_wt[off] = __float2half_rn(v);
            }
        }
    }
    grid_barrier(0);

    // ================= phase 1: GEMM + fused column stats =================
    {
        const int lane = tid & 31;
        const int wid  = tid >> 5;
        const int warp_m = wid & 3;          // 4 M-warps of 32 rows
        const int warp_n = wid >> 2;         // 2 N-warps of 64 cols
        const int o  = bid >> 2;
        const int mt = bid & 3;

        int nin[4];
        #pragma unroll
        for (int k = 0; k < 4; ++k) nin[k] = idx[(o << 2) + k];

        auto prefetch = [&](int c) {
            int k = c >> 1, dh = c & 1;
            uint32_t abuf = sbase + (uint32_t)(c % 3) * STAGE_BYTES;
            uint32_t bbuf = abuf + 16384;
            const __half* abase = g_xh + ((size_t)(mt * 128) * NIN + nin[k]) * DIN + dh * 64;
            const __half* bbase = g_wt + (size_t)o * (DOUT * KD) + k * DIN + dh * 64;
            #pragma unroll
            for (int it = 0; it < 4; ++it) {
                int v = it * 256 + tid;          // 1024 16B chunks per tile
                int row = v >> 3, cc = v & 7;
                uint32_t dsw = (uint32_t)row * 128 + (((uint32_t)cc * 16) ^ (((uint32_t)row & 7) << 4));
                cp_async16(abuf + dsw, abase + (size_t)row * (NIN * DIN) + cc * 8);
                cp_async16(bbuf + dsw, bbase + (size_t)row * KD + cc * 8);
            }
        };

        const int sub = lane >> 3;
        const int rowA = warp_m * 32 + (sub & 1) * 8 + (lane & 7);
        const int khA  = sub >> 1;
        const uint32_t swzA = ((uint32_t)rowA & 7) << 4;
        const int rowB = warp_n * 64 + (sub >> 1) * 8 + (lane & 7);
        const int khB  = sub & 1;
        const uint32_t swzB = ((uint32_t)rowB & 7) << 4;

        float acc[2][8][4];
        #pragma unroll
        for (int mi = 0; mi < 2; ++mi)
            #pragma unroll
            for (int ni = 0; ni < 8; ++ni)
                #pragma unroll
                for (int q = 0; q < 4; ++q) acc[mi][ni][q] = 0.0f;

        prefetch(0); cp_commit();
        prefetch(1); cp_commit();

        for (int c = 0; c < NCHUNK; ++c) {
            cp_wait<1>();
            __syncthreads();
            if (c + 2 < NCHUNK) prefetch(c + 2);
            cp_commit();

            uint32_t abuf = sbase + (uint32_t)(c % 3) * STAGE_BYTES;
            uint32_t bbuf = abuf + 16384;
            #pragma unroll
            for (int ks = 0; ks < 4; ++ks) {
                uint32_t ka = (((uint32_t)ks * 32 + (uint32_t)khA * 16) ^ swzA);
                uint32_t kb = (((uint32_t)ks * 32 + (uint32_t)khB * 16) ^ swzB);
                uint32_t a[2][4];
                ldsm_x4(a[0], abuf + (uint32_t)rowA * 128 + ka);
                ldsm_x4(a[1], abuf + (uint32_t)(rowA + 16) * 128 + ka);
                uint32_t b[4][4];
                #pragma unroll
                for (int nb = 0; nb < 4; ++nb)
                    ldsm_x4(b[nb], bbuf + (uint32_t)(rowB + nb * 16) * 128 + kb);
                #pragma unroll
                for (int mi = 0; mi < 2; ++mi)
                    #pragma unroll
                    for (int ni = 0; ni < 8; ++ni)
                        mma16816(acc[mi][ni], a[mi], b[ni >> 1][(ni & 1) * 2], b[ni >> 1][(ni & 1) * 2 + 1]);
            }
            __syncthreads();
        }

        // ---- epilogue 1: write fp32 tile to g_y ----
        const int r0 = mt * 128 + warp_m * 32 + (lane >> 2);
        const int col0 = o * DOUT + warp_n * 64 + (lane & 3) * 2;
        #pragma unroll
        for (int mi = 0; mi < 2; ++mi) {
            #pragma unroll
            for (int ni = 0; ni < 8; ++ni) {
                float* p0 = g_y + (size_t)(r0 + mi * 16) * YCOLS + col0 + ni * 8;
                float* p1 = p0 + 8 * YCOLS;
                *reinterpret_cast<float2*>(p0) = make_float2(acc[mi][ni][0], acc[mi][ni][1]);
                *reinterpret_cast<float2*>(p1) = make_float2(acc[mi][ni][2], acc[mi][ni][3]);
            }
        }

        // ---- epilogue 2: fused per-column sum/sumsq over this 128-row tile ----
        float csum[8][2], csq[8][2];
        #pragma unroll
        for (int ni = 0; ni < 8; ++ni) {
            #pragma unroll
            for (int q = 0; q < 2; ++q) {
                float a0 = acc[0][ni][q],     a1 = acc[0][ni][q + 2];
                float a2 = acc[1][ni][q],     a3 = acc[1][ni][q + 2];
                csum[ni][q] = (a0 + a1) + (a2 + a3);
                csq [ni][q] = fmaf(a0, a0, fmaf(a1, a1, fmaf(a2, a2, a3 * a3)));
            }
        }
        #pragma unroll
        for (int m = 4; m <= 16; m <<= 1) {
            #pragma unroll
            for (int ni = 0; ni < 8; ++ni) {
                #pragma unroll
                for (int q = 0; q < 2; ++q) {
                    csum[ni][q] += __shfl_xor_sync(0xFFFFFFFFu, csum[ni][q], m);
                    csq [ni][q] += __shfl_xor_sync(0xFFFFFFFFu, csq [ni][q], m);
                }
            }
        }
        float* s_sum = reinterpret_cast<float*>(sptr);          // [4][128]
        float* s_sq  = s_sum + 512;                              // [4][128]
        __syncthreads();
        if ((lane >> 2) == 0) {
            int cbase = warp_n * 64 + (lane & 3) * 2;
            #pragma unroll
            for (int ni = 0; ni < 8; ++ni) {
                #pragma unroll
                for (int q = 0; q < 2; ++q) {
                    s_sum[warp_m * 128 + cbase + ni * 8 + q] = csum[ni][q];
                    s_sq [warp_m * 128 + cbase + ni * 8 + q] = csq [ni][q];
                }
            }
        }
        __syncthreads();
        if (tid < 128) {
            float ts = (s_sum[tid] + s_sum[128 + tid]) + (s_sum[256 + tid] + s_sum[384 + tid]);
            float tq = (s_sq [tid] + s_sq [128 + tid]) + (s_sq [256 + tid] + s_sq [384 + tid]);
            g_psum[mt * YCOLS + o * DOUT + tid] = ts;
            g_psq [mt * YCOLS + o * DOUT + tid] = tq;
        }
    }
    grid_barrier(1);

    // ================= phase 2: finalize scale/shift (32 cols per CTA) =================
    if (tid < 32) {
        int j = bid * 32 + tid;
        float sum = 0.f, sq = 0.f;
        #pragma unroll
        for (int s = 0; s < NMT; ++s) {
            sum += g_psum[s * YCOLS + j];
            sq  += g_psq [s * YCOLS + j];
        }
        float inv = 1.0f / (float)B_DIM;
        float mean = sum * inv;
        float var  = fmaf(sq, inv, -mean * mean);
        float sc = gamma[j] * rsqrtf(var + BN_EPS);
        g_scale[j] = sc;
        g_shift[j] = fmaf(-mean, sc, beta[j]);
    }
    grid_barrier(2);

    // ================= phase 3: BN apply + SiLU =================
    {
        #pragma unroll 4
        for (int it = 0; it < 16; ++it) {
            int i = bid * 4096 + it * 256 + tid;
            float4 v = reinterpret_cast<const float4*>(g_y)[i];
            int col = (i << 2) & (YCOLS - 1);
            float4 sc = *reinterpret_cast<const float4*>(g_scale + col);
            float4 sh = *reinterpret_cast<const float4*>(g_shift + col);
            float y0 = fmaf(v.x, sc.x, sh.x);
            float y1 = fmaf(v.y, sc.y, sh.y);
            float y2 = fmaf(v.z, sc.z, sh.z);
            float y3 = fmaf(v.w, sc.w, sh.w);
            float4 r;
            r.x = y0 * rcp_fast(1.0f + __expf(-y0));
            r.y = y1 * rcp_fast(1.0f + __expf(-y1));
            r.z = y2 * rcp_fast(1.0f + __expf(-y2));
            r.w = y3 * rcp_fast(1.0f + __expf(-y3));
            reinterpret_cast<float4*>(out)[i] = r;
        }
    }
}

// ---------------- launch ----------------
extern "C" void kernel_launch(void* const* d_in, const int* in_sizes, int n_in,
                              void* d_out, int out_size) {
    const float* x     = (const float*)d_in[0];   // (512,64,128)
    const float* W     = (const float*)d_in[1];   // (64,4,128,128)
    // d_in[2] = bias: provably cancelled by BatchNorm (batch-constant shift) — unused.
    const float* gamma = (const float*)d_in[3];   // (8192)
    const float* beta  = (const float*)d_in[4];   // (8192)
    const int*   idx   = (const int*)d_in[5];     // (64,4)
    float* out = (float*)d_out;

    cudaFuncSetAttribute(eb_mega, cudaFuncAttributeMaxDynamicSharedMemorySize, GEMM_SMEM_BYTES);
    eb_mega<<<NCTA, 256, GEMM_SMEM_BYTES>>>(x, W, gamma, beta, idx, out);
}

// round 8
// speedup vs baseline: 2.6901x; 1.2890x over previous
#include <cuda_runtime.h>
#include <cuda_fp16.h>
#include <cstdint>

// ---------------- problem dims ----------------
#define B_DIM 512
#define NIN   64
#define DIN   128
#define NOUT  64
#define DOUT  128
#define KSEL  4
#define YCOLS (NOUT * DOUT)        // 8192
#define BN_EPS 1e-5f

#define KD      (KSEL * DIN)       // 512 (logical K per head)
#define NCHUNK  8                  // 4 k-sel x 2 half-DIN; 64 fp16 per chunk
#define NMT     4                  // M-tiles per head (partial-stats slots)
#define NCTA    256                // mega-kernel grid (all co-resident: 2/SM x 148 SMs = 296 max)

// ---------------- scratch (device globals; no allocation allowed) ----------------
__device__ __align__(16) __half  g_xh[B_DIM * NIN * DIN];     // 8.4 MB
__device__ __align__(16) __half  g_wt[NOUT * DOUT * KD];      // [o][e][k*128+d], 8.4 MB
__device__ __align__(16) float   g_scale[YCOLS];
__device__ __align__(16) float   g_shift[YCOLS];
__device__ __align__(16) float   g_psum[NMT * YCOLS];         // 128 KB
__device__ __align__(16) float   g_psq [NMT * YCOLS];         // 128 KB
__device__ unsigned int          g_bar[4];                    // monotonic ticket barriers

// ---------------- helpers ----------------
__device__ __forceinline__ uint32_t smem_u32(const void* p) {
    uint32_t a;
    asm("{ .reg .u64 t; cvta.to.shared.u64 t, %1; cvt.u32.u64 %0, t; }" : "=r"(a) : "l"(p));
    return a;
}
__device__ __forceinline__ void cp_async16(uint32_t dst, const void* src) {
    asm volatile("cp.async.cg.shared.global [%0], [%1], 16;" :: "r"(dst), "l"(src) : "memory");
}
__device__ __forceinline__ void cp_commit() {
    asm volatile("cp.async.commit_group;" ::: "memory");
}
template <int N>
__device__ __forceinline__ void cp_wait() {
    asm volatile("cp.async.wait_group %0;" :: "n"(N) : "memory");
}
__device__ __forceinline__ void ldsm_x4(uint32_t* r, uint32_t addr) {
    asm volatile("ldmatrix.sync.aligned.m8n8.x4.shared.b16 {%0,%1,%2,%3}, [%4];"
                 : "=r"(r[0]), "=r"(r[1]), "=r"(r[2]), "=r"(r[3]) : "r"(addr));
}
__device__ __forceinline__ void mma16816(float* d, const uint32_t* a, uint32_t b0, uint32_t b1) {
    asm volatile(
        "mma.sync.aligned.m16n8k16.row.col.f32.f16.f16.f32 "
        "{%0,%1,%2,%3}, {%4,%5,%6,%7}, {%8,%9}, {%0,%1,%2,%3};"
        : "+f"(d[0]), "+f"(d[1]), "+f"(d[2]), "+f"(d[3])
        : "r"(a[0]), "r"(a[1]), "r"(a[2]), "r"(a[3]), "r"(b0), "r"(b1));
}
__device__ __forceinline__ float rcp_fast(float x) {
    float r;
    asm("rcp.approx.f32 %0, %1;" : "=f"(r) : "f"(x));
    return r;
}

// Grid-wide barrier: monotonic ticket counter, no reset needed (replay-safe).
// All NCTA CTAs are guaranteed co-resident (one wave), so spinning is deadlock-free.
__device__ __forceinline__ void grid_barrier(int slot) {
    __syncthreads();
    if (threadIdx.x == 0) {
        __threadfence();
        unsigned ticket = atomicAdd(&g_bar[slot], 1u);
        unsigned target = (ticket / NCTA + 1u) * NCTA;
        unsigned v;
        do {
            asm volatile("ld.acquire.gpu.u32 %0, [%1];"
                         : "=r"(v) : "l"(&g_bar[slot]));
        } while ((int)(v - target) < 0);
    }
    __syncthreads();
}

// ---------------- THE mega kernel ----------------
// Phases: [conv x + conv/transpose W] -> bar -> [GEMM, stats from registers]
//         -> bar -> [finalize scale/shift] -> bar -> [BN+SiLU applied to the
//         STILL-LIVE register tile, written straight to out]. No g_y buffer.
#define STAGE_BYTES 32768
#define GEMM_SMEM_BYTES (3 * STAGE_BYTES + 1024)

__global__ void __launch_bounds__(256, 2)
eb_mega(const float* __restrict__ x, const float* __restrict__ W,
        const float* __restrict__ gamma, const float* __restrict__ beta,
        const int* __restrict__ idx, float* __restrict__ out) {
    extern __shared__ char dsm[];
    uint32_t raw = smem_u32(dsm);
    uint32_t sbase = (raw + 1023u) & ~1023u;
    char* sptr = dsm + (sbase - raw);

    const int tid  = threadIdx.x;
    const int bid  = blockIdx.x;

    // ================= phase 0: convert inputs =================
    {
        const float4* xin = reinterpret_cast<const float4*>(x);
        #pragma unroll 4
        for (int it = 0; it < 16; ++it) {
            int i = bid * 4096 + it * 256 + tid;
            float4 v = xin[i];
            __half2 p0 = __floats2half2_rn(v.x, v.y);
            __half2 p1 = __floats2half2_rn(v.z, v.w);
            uint2 pk;
            pk.x = *reinterpret_cast<uint32_t*>(&p0);
            pk.y = *reinterpret_cast<uint32_t*>(&p1);
            reinterpret_cast<uint2*>(g_xh)[i] = pk;
        }
        float* tile = reinterpret_cast<float*>(sptr);   // [128][33]
        int o = bid >> 2, k = bid & 3;
        const float* src = W + (size_t)bid * (DIN * DOUT);   // W[o][k][d][e]
        for (int eb = 0; eb < 4; ++eb) {
            __syncthreads();
            #pragma unroll
            for (int it = 0; it < 16; ++it) {
                int flat = it * 256 + tid;
                int d = flat >> 5, e2 = flat & 31;
                tile[d * 33 + e2] = src[d * DOUT + eb * 32 + e2];
            }
            __syncthreads();
            #pragma unroll
            for (int it = 0; it < 16; ++it) {
                int flat = it * 256 + tid;
                int e2 = flat >> 7, d = flat & 127;
                float v = tile[d * 33 + e2];
                size_t off = (size_t)o * (DOUT * KD) + (size_t)(eb * 32 + e2) * KD + k * DIN + d;
                g_wt[off] = __float2half_rn(v);
            }
        }
    }
    grid_barrier(0);

    // ================= phase 1: GEMM + stats (accumulators stay live) =================
    const int lane = tid & 31;
    const int wid  = tid >> 5;
    const int warp_m = wid & 3;          // 4 M-warps of 32 rows
    const int warp_n = wid >> 2;         // 2 N-warps of 64 cols
    const int o  = bid >> 2;
    const int mt = bid & 3;

    float acc[2][8][4];
    #pragma unroll
    for (int mi = 0; mi < 2; ++mi)
        #pragma unroll
        for (int ni = 0; ni < 8; ++ni)
            #pragma unroll
            for (int q = 0; q < 4; ++q) acc[mi][ni][q] = 0.0f;

    {
        int nin[4];
        #pragma unroll
        for (int k = 0; k < 4; ++k) nin[k] = idx[(o << 2) + k];

        auto prefetch = [&](int c) {
            int k = c >> 1, dh = c & 1;
            uint32_t abuf = sbase + (uint32_t)(c % 3) * STAGE_BYTES;
            uint32_t bbuf = abuf + 16384;
            const __half* abase = g_xh + ((size_t)(mt * 128) * NIN + nin[k]) * DIN + dh * 64;
            const __half* bbase = g_wt + (size_t)o * (DOUT * KD) + k * DIN + dh * 64;
            #pragma unroll
            for (int it = 0; it < 4; ++it) {
                int v = it * 256 + tid;          // 1024 16B chunks per tile
                int row = v >> 3, cc = v & 7;
                uint32_t dsw = (uint32_t)row * 128 + (((uint32_t)cc * 16) ^ (((uint32_t)row & 7) << 4));
                cp_async16(abuf + dsw, abase + (size_t)row * (NIN * DIN) + cc * 8);
                cp_async16(bbuf + dsw, bbase + (size_t)row * KD + cc * 8);
            }
        };

        const int sub = lane >> 3;
        const int rowA = warp_m * 32 + (sub & 1) * 8 + (lane & 7);
        const int khA  = sub >> 1;
        const uint32_t swzA = ((uint32_t)rowA & 7) << 4;
        const int rowB = warp_n * 64 + (sub >> 1) * 8 + (lane & 7);
        const int khB  = sub & 1;
        const uint32_t swzB = ((uint32_t)rowB & 7) << 4;

        prefetch(0); cp_commit();
        prefetch(1); cp_commit();

        for (int c = 0; c < NCHUNK; ++c) {
            cp_wait<1>();
            __syncthreads();
            if (c + 2 < NCHUNK) prefetch(c + 2);
            cp_commit();

            uint32_t abuf = sbase + (uint32_t)(c % 3) * STAGE_BYTES;
            uint32_t bbuf = abuf + 16384;
            #pragma unroll
            for (int ks = 0; ks < 4; ++ks) {
                uint32_t ka = (((uint32_t)ks * 32 + (uint32_t)khA * 16) ^ swzA);
                uint32_t kb = (((uint32_t)ks * 32 + (uint32_t)khB * 16) ^ swzB);
                uint32_t a[2][4];
                ldsm_x4(a[0], abuf + (uint32_t)rowA * 128 + ka);
                ldsm_x4(a[1], abuf + (uint32_t)(rowA + 16) * 128 + ka);
                uint32_t b[4][4];
                #pragma unroll
                for (int nb = 0; nb < 4; ++nb)
                    ldsm_x4(b[nb], bbuf + (uint32_t)(rowB + nb * 16) * 128 + kb);
                #pragma unroll
                for (int mi = 0; mi < 2; ++mi)
                    #pragma unroll
                    for (int ni = 0; ni < 8; ++ni)
                        mma16816(acc[mi][ni], a[mi], b[ni >> 1][(ni & 1) * 2], b[ni >> 1][(ni & 1) * 2 + 1]);
            }
            __syncthreads();
        }

        // ---- stats from registers: per-column sum/sumsq over this 128-row tile ----
        float csum[8][2], csq[8][2];
        #pragma unroll
        for (int ni = 0; ni < 8; ++ni) {
            #pragma unroll
            for (int q = 0; q < 2; ++q) {
                float a0 = acc[0][ni][q],     a1 = acc[0][ni][q + 2];
                float a2 = acc[1][ni][q],     a3 = acc[1][ni][q + 2];
                csum[ni][q] = (a0 + a1) + (a2 + a3);
                csq [ni][q] = fmaf(a0, a0, fmaf(a1, a1, fmaf(a2, a2, a3 * a3)));
            }
        }
        #pragma unroll
        for (int m = 4; m <= 16; m <<= 1) {
            #pragma unroll
            for (int ni = 0; ni < 8; ++ni) {
                #pragma unroll
                for (int q = 0; q < 2; ++q) {
                    csum[ni][q] += __shfl_xor_sync(0xFFFFFFFFu, csum[ni][q], m);
                    csq [ni][q] += __shfl_xor_sync(0xFFFFFFFFu, csq [ni][q], m);
                }
            }
        }
        float* s_sum = reinterpret_cast<float*>(sptr);          // [4][128]
        float* s_sq  = s_sum + 512;                              // [4][128]
        __syncthreads();
        if ((lane >> 2) == 0) {
            int cbase = warp_n * 64 + (lane & 3) * 2;
            #pragma unroll
            for (int ni = 0; ni < 8; ++ni) {
                #pragma unroll
                for (int q = 0; q < 2; ++q) {
                    s_sum[warp_m * 128 + cbase + ni * 8 + q] = csum[ni][q];
                    s_sq [warp_m * 128 + cbase + ni * 8 + q] = csq [ni][q];
                }
            }
        }
        __syncthreads();
        if (tid < 128) {
            float ts = (s_sum[tid] + s_sum[128 + tid]) + (s_sum[256 + tid] + s_sum[384 + tid]);
            float tq = (s_sq [tid] + s_sq [128 + tid]) + (s_sq [256 + tid] + s_sq [384 + tid]);
            g_psum[mt * YCOLS + o * DOUT + tid] = ts;
            g_psq [mt * YCOLS + o * DOUT + tid] = tq;
        }
    }
    grid_barrier(1);

    // ================= phase 2: finalize scale/shift (32 cols per CTA) =================
    if (tid < 32) {
        int j = bid * 32 + tid;
        float sum = 0.f, sq = 0.f;
        #pragma unroll
        for (int s = 0; s < NMT; ++s) {
            sum += g_psum[s * YCOLS + j];
            sq  += g_psq [s * YCOLS + j];
        }
        float inv = 1.0f / (float)B_DIM;
        float mean = sum * inv;
        float var  = fmaf(sq, inv, -mean * mean);
        float sc = gamma[j] * rsqrtf(var + BN_EPS);
        g_scale[j] = sc;
        g_shift[j] = fmaf(-mean, sc, beta[j]);
    }
    grid_barrier(2);

    // ================= phase 3: BN + SiLU on the register tile -> out =================
    {
        const int r0 = mt * 128 + warp_m * 32 + (lane >> 2);
        const int col0 = o * DOUT + warp_n * 64 + (lane & 3) * 2;
        #pragma unroll
        for (int ni = 0; ni < 8; ++ni) {
            float2 sc = *reinterpret_cast<const float2*>(g_scale + col0 + ni * 8);
            float2 sh = *reinterpret_cast<const float2*>(g_shift + col0 + ni * 8);
            #pragma unroll
            for (int mi = 0; mi < 2; ++mi) {
                float y0 = fmaf(acc[mi][ni][0], sc.x, sh.x);
                float y1 = fmaf(acc[mi][ni][1], sc.y, sh.y);
                float y2 = fmaf(acc[mi][ni][2], sc.x, sh.x);
                float y3 = fmaf(acc[mi][ni][3], sc.y, sh.y);
                float2 r0v, r1v;
                r0v.x = y0 * rcp_fast(1.0f + __expf(-y0));
                r0v.y = y1 * rcp_fast(1.0f + __expf(-y1));
                r1v.x = y2 * rcp_fast(1.0f + __expf(-y2));
                r1v.y = y3 * rcp_fast(1.0f + __expf(-y3));
                float* p0 = out + (size_t)(r0 + mi * 16) * YCOLS + col0 + ni * 8;
                *reinterpret_cast<float2*>(p0) = r0v;
                *reinterpret_cast<float2*>(p0 + 8 * YCOLS) = r1v;
            }
        }
    }
}

// ---------------- launch ----------------
extern "C" void kernel_launch(void* const* d_in, const int* in_sizes, int n_in,
                              void* d_out, int out_size) {
    const float* x     = (const float*)d_in[0];   // (512,64,128)
    const float* W     = (const float*)d_in[1];   // (64,4,128,128)
    // d_in[2] = bias: provably cancelled by BatchNorm (batch-constant shift) — unused.
    const float* gamma = (const float*)d_in[3];   // (8192)
    const float* beta  = (const float*)d_in[4];   // (8192)
    const int*   idx   = (const int*)d_in[5];     // (64,4)
    float* out = (float*)d_out;

    cudaFuncSetAttribute(eb_mega, cudaFuncAttributeMaxDynamicSharedMemorySize, GEMM_SMEM_BYTES);
    eb_mega<<<NCTA, 256, GEMM_SMEM_BYTES>>>(x, W, gamma, beta, idx, out);
}